// round 14
// baseline (speedup 1.0000x reference)
#include <cuda_runtime.h>
#include <cstdint>

#define NN 100000
#define IN_CH 64
#define HID 64
#define N_CLS 40

// Scratch (allocation-free contract: __device__ globals).
// float4 => 16B-aligned base, required by red.global.add.v4.f32.
__device__ float4 g_Y4 [(size_t)NN * (HID / 4)];   // Y, later reused for H2
__device__ float4 g_H14[(size_t)NN * (HID / 4)];
__device__ float4 g_Z4 [(size_t)NN * (HID / 4)];
__device__ int    g_deg[NN];

// ---------------------------------------------------------------------------
// Dense layer 1 + fused scratch zeroing.
// Y = relu(NF @ W1 + b1), thread-per-row, W1 in smem.
// Each thread also zeroes its H1 row, Z row and deg entry.
// ---------------------------------------------------------------------------
__global__ void __launch_bounds__(256) dense1_kernel(
    const float* __restrict__ nf, const float* __restrict__ W1,
    const float* __restrict__ b1, int n)
{
    __shared__ float Ws[IN_CH * HID];
    __shared__ float bs[HID];
    for (int i = threadIdx.x; i < IN_CH * HID; i += blockDim.x) Ws[i] = W1[i];
    for (int i = threadIdx.x; i < HID; i += blockDim.x) bs[i] = b1[i];
    __syncthreads();

    int row = blockIdx.x * blockDim.x + threadIdx.x;
    if (row >= n) return;

    {
        float4 z4 = make_float4(0.f, 0.f, 0.f, 0.f);
        float4* h1r = g_H14 + (size_t)row * (HID / 4);
        float4* zr  = g_Z4  + (size_t)row * (HID / 4);
        #pragma unroll
        for (int j = 0; j < HID / 4; j++) { h1r[j] = z4; zr[j] = z4; }
        g_deg[row] = 0;
    }

    float x[IN_CH];
    const float4* xr = reinterpret_cast<const float4*>(nf + (size_t)row * IN_CH);
    #pragma unroll
    for (int k4 = 0; k4 < IN_CH / 4; k4++) {
        float4 v = xr[k4];
        x[4*k4+0] = v.x; x[4*k4+1] = v.y; x[4*k4+2] = v.z; x[4*k4+3] = v.w;
    }

    float4* yr = g_Y4 + (size_t)row * (HID / 4);
    #pragma unroll 1
    for (int jj = 0; jj < HID / 4; jj++) {
        float4 acc = *reinterpret_cast<const float4*>(bs + jj * 4);
        #pragma unroll
        for (int k = 0; k < IN_CH; k++) {
            float4 w = *reinterpret_cast<const float4*>(Ws + k * HID + jj * 4);
            acc.x = fmaf(x[k], w.x, acc.x);
            acc.y = fmaf(x[k], w.y, acc.y);
            acc.z = fmaf(x[k], w.z, acc.z);
            acc.w = fmaf(x[k], w.w, acc.w);
        }
        acc.x = fmaxf(acc.x, 0.f); acc.y = fmaxf(acc.y, 0.f);
        acc.z = fmaxf(acc.z, 0.f); acc.w = fmaxf(acc.w, 0.f);
        yr[jj] = acc;
    }
}

// ---------------------------------------------------------------------------
// Edge-parallel scatter-add (round-4 form — fastest measured).
// 16 threads per edge, each moving one float4 via vector red.global.
// PASS==0: Y -> H1 (+ degree histogram);  PASS==1: H1 -> Z
// ---------------------------------------------------------------------------
template <int PASS>
__global__ void __launch_bounds__(256) scatter_kernel(
    const int* __restrict__ ei, int E)
{
    long long tid = (long long)blockIdx.x * blockDim.x + threadIdx.x;
    int e = (int)(tid >> 4);
    if (e >= E) return;
    int c = (int)(tid & 15);

    int s = __ldg(ei + e);
    int d = __ldg(ei + E + e);

    const float4* srct = (PASS == 0) ? g_Y4  : g_H14;
    float4*       dstt = (PASS == 0) ? g_H14 : g_Z4;

    float4 v = __ldg(&srct[(size_t)s * (HID / 4) + c]);
    float4* p = dstt + (size_t)d * (HID / 4) + c;
    unsigned long long gp = (unsigned long long)__cvta_generic_to_global(p);
    asm volatile("red.global.add.v4.f32 [%0], {%1, %2, %3, %4};"
                 :: "l"(gp), "f"(v.x), "f"(v.y), "f"(v.z), "f"(v.w)
                 : "memory");

    if (PASS == 0 && c == 0) atomicAdd(&g_deg[d], 1);
}

// ---------------------------------------------------------------------------
// k2a: H2 = Z@W2 + deg*b2 -> g_Y4 (reused scratch; Y dead after scatter<0>).
// Thread-per-row, dense1-like register profile.
// ---------------------------------------------------------------------------
__global__ void __launch_bounds__(256) dense2a_kernel(
    const float* __restrict__ W2, const float* __restrict__ b2, int n)
{
    __shared__ float Ws[HID * HID];
    __shared__ float bs[HID];
    for (int i = threadIdx.x; i < HID * HID; i += blockDim.x) Ws[i] = W2[i];
    for (int i = threadIdx.x; i < HID; i += blockDim.x) bs[i] = b2[i];
    __syncthreads();

    int row = blockIdx.x * blockDim.x + threadIdx.x;
    if (row >= n) return;

    float z[HID];
    const float4* zr = g_Z4 + (size_t)row * (HID / 4);
    #pragma unroll
    for (int k4 = 0; k4 < HID / 4; k4++) {
        float4 v = zr[k4];
        z[4*k4+0] = v.x; z[4*k4+1] = v.y; z[4*k4+2] = v.z; z[4*k4+3] = v.w;
    }
    float degf = (float)__ldg(&g_deg[row]);

    float4* hr = g_Y4 + (size_t)row * (HID / 4);
    #pragma unroll 1
    for (int jj = 0; jj < HID / 4; jj++) {
        float4 b = *reinterpret_cast<const float4*>(bs + jj * 4);
        float4 acc = make_float4(degf * b.x, degf * b.y, degf * b.z, degf * b.w);
        #pragma unroll
        for (int k = 0; k < HID; k++) {
            float4 w = *reinterpret_cast<const float4*>(Ws + k * HID + jj * 4);
            acc.x = fmaf(z[k], w.x, acc.x);
            acc.y = fmaf(z[k], w.y, acc.y);
            acc.z = fmaf(z[k], w.z, acc.z);
            acc.w = fmaf(z[k], w.w, acc.w);
        }
        hr[jj] = acc;
    }
}

// ---------------------------------------------------------------------------
// k2b: logits = H2@Wf + bf; softmax -> out. Thread-per-row.
// H2 row is STREAMED 4 floats at a time (never held whole) so only
// logits[40] stays live -> low register pressure, high occupancy.
// ---------------------------------------------------------------------------
__global__ void __launch_bounds__(256) dense2b_kernel(
    const float* __restrict__ Wf, const float* __restrict__ bf,
    float* __restrict__ out, int n)
{
    __shared__ float Ws[HID * N_CLS];
    __shared__ float bs[N_CLS];
    for (int i = threadIdx.x; i < HID * N_CLS; i += blockDim.x) Ws[i] = Wf[i];
    for (int i = threadIdx.x; i < N_CLS; i += blockDim.x) bs[i] = bf[i];
    __syncthreads();

    int row = blockIdx.x * blockDim.x + threadIdx.x;
    if (row >= n) return;

    float logits[N_CLS];
    #pragma unroll
    for (int cc = 0; cc < N_CLS; cc++) logits[cc] = bs[cc];

    const float4* hr = g_Y4 + (size_t)row * (HID / 4);
    #pragma unroll 1
    for (int k4 = 0; k4 < HID / 4; k4++) {
        float4 h = __ldg(&hr[k4]);
        const float* w0 = Ws + (k4 * 4 + 0) * N_CLS;
        const float* w1 = Ws + (k4 * 4 + 1) * N_CLS;
        const float* w2 = Ws + (k4 * 4 + 2) * N_CLS;
        const float* w3 = Ws + (k4 * 4 + 3) * N_CLS;
        #pragma unroll
        for (int cc = 0; cc < N_CLS; cc++) {
            float acc = logits[cc];
            acc = fmaf(h.x, w0[cc], acc);
            acc = fmaf(h.y, w1[cc], acc);
            acc = fmaf(h.z, w2[cc], acc);
            acc = fmaf(h.w, w3[cc], acc);
            logits[cc] = acc;
        }
    }

    float m = logits[0];
    #pragma unroll
    for (int cc = 1; cc < N_CLS; cc++) m = fmaxf(m, logits[cc]);
    float ssum = 0.f;
    #pragma unroll
    for (int cc = 0; cc < N_CLS; cc++) {
        float ev = __expf(logits[cc] - m);
        logits[cc] = ev;
        ssum += ev;
    }
    float inv = 1.f / ssum;
    float* orow = out + (size_t)row * N_CLS;
    #pragma unroll
    for (int c4 = 0; c4 < N_CLS / 4; c4++) {
        float4 o;
        o.x = logits[c4*4+0] * inv; o.y = logits[c4*4+1] * inv;
        o.z = logits[c4*4+2] * inv; o.w = logits[c4*4+3] * inv;
        *reinterpret_cast<float4*>(orow + c4 * 4) = o;
    }
}

// ---------------------------------------------------------------------------
extern "C" void kernel_launch(void* const* d_in, const int* in_sizes, int n_in,
                              void* d_out, int out_size)
{
    const float* nf = (const float*)d_in[0];
    const int*   ei = (const int*)d_in[1];   // int32 (JAX x64 disabled)
    const float* W1 = (const float*)d_in[2];
    const float* b1 = (const float*)d_in[3];
    const float* W2 = (const float*)d_in[4];
    const float* b2 = (const float*)d_in[5];
    const float* Wf = (const float*)d_in[6];
    const float* bf = (const float*)d_in[7];
    float* out = (float*)d_out;

    int n = in_sizes[0] / IN_CH;   // 100000
    int E = in_sizes[1] / 2;       // 1600000

    dense1_kernel<<<(n + 255) / 256, 256>>>(nf, W1, b1, n);  // also zeroes H1/Z/deg

    long long work = (long long)E * 16;
    int sblocks = (int)((work + 255) / 256);
    scatter_kernel<0><<<sblocks, 256>>>(ei, E);
    scatter_kernel<1><<<sblocks, 256>>>(ei, E);

    dense2a_kernel<<<(n + 255) / 256, 256>>>(W2, b2, n);     // H2 -> g_Y4
    dense2b_kernel<<<(n + 255) / 256, 256>>>(Wf, bf, out, n);
}

// round 15
// speedup vs baseline: 1.1816x; 1.1816x over previous
#include <cuda_runtime.h>
#include <cstdint>

#define NN 100000
#define IN_CH 64
#define HID 64
#define N_CLS 40

// Scratch (allocation-free contract: __device__ globals).
// float4 => 16B-aligned base, required by red.global.add.v4.f32.
__device__ float4 g_Y4 [(size_t)NN * (HID / 4)];   // Y, later reused for H2
__device__ float4 g_H14[(size_t)NN * (HID / 4)];
__device__ float4 g_Z4 [(size_t)NN * (HID / 4)];
__device__ int    g_deg[NN];

// ---------------------------------------------------------------------------
// Register-tiled 64x64 GEMM: block = 64 rows, thread = 4 rows x 4 cols.
// Per k: 1 LDS.128 (w) + 4 broadcast LDS.32 (z) -> 16 FMA. LDS traffic is
// amortized 4x across the row tile vs thread-per-row.
// MODE 0 (dense1): src = nf, out = relu(src@W + b) -> g_Y4; also zeroes
//                  H1/Z/deg for this block's rows (replaces zero pass).
// MODE 1 (dense2a): src = g_Z4, out = src@W + deg*b -> g_Y4 (H2).
// ---------------------------------------------------------------------------
template <int MODE>
__global__ void __launch_bounds__(256) gemm64_kernel(
    const float* __restrict__ Xg,   // MODE 0: nf; MODE 1: ignored
    const float* __restrict__ W,    // [64,64] row-major (k, col)
    const float* __restrict__ b,    // [64]
    int n)
{
    __shared__ float Ws[64 * 64];
    __shared__ float Xs[64 * 64];

    int tid = threadIdx.x;
    int rb  = blockIdx.x * 64;           // first row of this block

    const float4* src4 = (MODE == 0) ? (const float4*)Xg : g_Z4;

    // stage W (1024 float4)
    #pragma unroll
    for (int it = 0; it < 4; it++) {
        int ii = tid + it * 256;
        reinterpret_cast<float4*>(Ws)[ii] =
            __ldg(&reinterpret_cast<const float4*>(W)[ii]);
    }
    // stage X rows rb..rb+63 (guarded), scalar-store into Xs[row][k]
    #pragma unroll
    for (int it = 0; it < 4; it++) {
        int ii = tid + it * 256;         // 0..1023
        int rl = ii >> 4;                // local row
        int k4 = ii & 15;
        int gr = rb + rl;
        float4 v = make_float4(0.f, 0.f, 0.f, 0.f);
        if (gr < n) v = __ldg(&src4[(size_t)gr * 16 + k4]);
        float* xp = Xs + rl * 64 + k4 * 4;
        xp[0] = v.x; xp[1] = v.y; xp[2] = v.z; xp[3] = v.w;
    }

    if (MODE == 0) {
        // fused zeroing of H1, Z, deg for this block's rows
        float4 z4 = make_float4(0.f, 0.f, 0.f, 0.f);
        int lim = n * 16;
        #pragma unroll
        for (int it = 0; it < 4; it++) {
            int idx = rb * 16 + tid + it * 256;
            if (idx < lim) { g_H14[idx] = z4; g_Z4[idx] = z4; }
        }
        if (tid < 64 && rb + tid < n) g_deg[rb + tid] = 0;
    }
    __syncthreads();

    int rg = tid >> 4;                    // row group 0..15
    int cg = tid & 15;                    // col group 0..15
    int r0 = rg * 4;
    int c0 = cg * 4;

    float4 bv = __ldg(reinterpret_cast<const float4*>(b + c0));

    float acc[4][4];
    if (MODE == 0) {
        #pragma unroll
        for (int i = 0; i < 4; i++) {
            acc[i][0] = bv.x; acc[i][1] = bv.y; acc[i][2] = bv.z; acc[i][3] = bv.w;
        }
    } else {
        #pragma unroll
        for (int i = 0; i < 4; i++) {
            int gr = rb + r0 + i;
            float degf = (gr < n) ? (float)__ldg(&g_deg[gr]) : 0.f;
            acc[i][0] = degf * bv.x; acc[i][1] = degf * bv.y;
            acc[i][2] = degf * bv.z; acc[i][3] = degf * bv.w;
        }
    }

    #pragma unroll 4
    for (int k = 0; k < 64; k++) {
        float4 w = *reinterpret_cast<const float4*>(Ws + k * 64 + c0);
        float z0 = Xs[(r0 + 0) * 64 + k];
        float z1 = Xs[(r0 + 1) * 64 + k];
        float z2 = Xs[(r0 + 2) * 64 + k];
        float z3 = Xs[(r0 + 3) * 64 + k];
        acc[0][0] = fmaf(z0, w.x, acc[0][0]); acc[0][1] = fmaf(z0, w.y, acc[0][1]);
        acc[0][2] = fmaf(z0, w.z, acc[0][2]); acc[0][3] = fmaf(z0, w.w, acc[0][3]);
        acc[1][0] = fmaf(z1, w.x, acc[1][0]); acc[1][1] = fmaf(z1, w.y, acc[1][1]);
        acc[1][2] = fmaf(z1, w.z, acc[1][2]); acc[1][3] = fmaf(z1, w.w, acc[1][3]);
        acc[2][0] = fmaf(z2, w.x, acc[2][0]); acc[2][1] = fmaf(z2, w.y, acc[2][1]);
        acc[2][2] = fmaf(z2, w.z, acc[2][2]); acc[2][3] = fmaf(z2, w.w, acc[2][3]);
        acc[3][0] = fmaf(z3, w.x, acc[3][0]); acc[3][1] = fmaf(z3, w.y, acc[3][1]);
        acc[3][2] = fmaf(z3, w.z, acc[3][2]); acc[3][3] = fmaf(z3, w.w, acc[3][3]);
    }

    #pragma unroll
    for (int i = 0; i < 4; i++) {
        int gr = rb + r0 + i;
        if (gr >= n) continue;
        float4 o;
        if (MODE == 0) {
            o.x = fmaxf(acc[i][0], 0.f); o.y = fmaxf(acc[i][1], 0.f);
            o.z = fmaxf(acc[i][2], 0.f); o.w = fmaxf(acc[i][3], 0.f);
        } else {
            o.x = acc[i][0]; o.y = acc[i][1]; o.z = acc[i][2]; o.w = acc[i][3];
        }
        g_Y4[(size_t)gr * 16 + cg] = o;
    }
}

// ---------------------------------------------------------------------------
// Edge-parallel scatter-add (round-4 form — fastest measured).
// 16 threads per edge, each moving one float4 via vector red.global.
// PASS==0: Y -> H1 (+ degree histogram);  PASS==1: H1 -> Z
// ---------------------------------------------------------------------------
template <int PASS>
__global__ void __launch_bounds__(256) scatter_kernel(
    const int* __restrict__ ei, int E)
{
    long long tid = (long long)blockIdx.x * blockDim.x + threadIdx.x;
    int e = (int)(tid >> 4);
    if (e >= E) return;
    int c = (int)(tid & 15);

    int s = __ldg(ei + e);
    int d = __ldg(ei + E + e);

    const float4* srct = (PASS == 0) ? g_Y4  : g_H14;
    float4*       dstt = (PASS == 0) ? g_H14 : g_Z4;

    float4 v = __ldg(&srct[(size_t)s * (HID / 4) + c]);
    float4* p = dstt + (size_t)d * (HID / 4) + c;
    unsigned long long gp = (unsigned long long)__cvta_generic_to_global(p);
    asm volatile("red.global.add.v4.f32 [%0], {%1, %2, %3, %4};"
                 :: "l"(gp), "f"(v.x), "f"(v.y), "f"(v.z), "f"(v.w)
                 : "memory");

    if (PASS == 0 && c == 0) atomicAdd(&g_deg[d], 1);
}

// ---------------------------------------------------------------------------
// dense2b: logits = H2@Wf + bf; softmax -> out. Thread-per-row, H2 streamed.
// ---------------------------------------------------------------------------
__global__ void __launch_bounds__(256) dense2b_kernel(
    const float* __restrict__ Wf, const float* __restrict__ bf,
    float* __restrict__ out, int n)
{
    __shared__ float Ws[HID * N_CLS];
    __shared__ float bs[N_CLS];
    for (int i = threadIdx.x; i < HID * N_CLS; i += blockDim.x) Ws[i] = Wf[i];
    for (int i = threadIdx.x; i < N_CLS; i += blockDim.x) bs[i] = bf[i];
    __syncthreads();

    int row = blockIdx.x * blockDim.x + threadIdx.x;
    if (row >= n) return;

    float logits[N_CLS];
    #pragma unroll
    for (int cc = 0; cc < N_CLS; cc++) logits[cc] = bs[cc];

    const float4* hr = g_Y4 + (size_t)row * (HID / 4);
    #pragma unroll 1
    for (int k4 = 0; k4 < HID / 4; k4++) {
        float4 h = __ldg(&hr[k4]);
        const float* w0 = Ws + (k4 * 4 + 0) * N_CLS;
        const float* w1 = Ws + (k4 * 4 + 1) * N_CLS;
        const float* w2 = Ws + (k4 * 4 + 2) * N_CLS;
        const float* w3 = Ws + (k4 * 4 + 3) * N_CLS;
        #pragma unroll
        for (int cc = 0; cc < N_CLS; cc++) {
            float acc = logits[cc];
            acc = fmaf(h.x, w0[cc], acc);
            acc = fmaf(h.y, w1[cc], acc);
            acc = fmaf(h.z, w2[cc], acc);
            acc = fmaf(h.w, w3[cc], acc);
            logits[cc] = acc;
        }
    }

    float m = logits[0];
    #pragma unroll
    for (int cc = 1; cc < N_CLS; cc++) m = fmaxf(m, logits[cc]);
    float ssum = 0.f;
    #pragma unroll
    for (int cc = 0; cc < N_CLS; cc++) {
        float ev = __expf(logits[cc] - m);
        logits[cc] = ev;
        ssum += ev;
    }
    float inv = 1.f / ssum;
    float* orow = out + (size_t)row * N_CLS;
    #pragma unroll
    for (int c4 = 0; c4 < N_CLS / 4; c4++) {
        float4 o;
        o.x = logits[c4*4+0] * inv; o.y = logits[c4*4+1] * inv;
        o.z = logits[c4*4+2] * inv; o.w = logits[c4*4+3] * inv;
        *reinterpret_cast<float4*>(orow + c4 * 4) = o;
    }
}

// ---------------------------------------------------------------------------
extern "C" void kernel_launch(void* const* d_in, const int* in_sizes, int n_in,
                              void* d_out, int out_size)
{
    const float* nf = (const float*)d_in[0];
    const int*   ei = (const int*)d_in[1];   // int32 (JAX x64 disabled)
    const float* W1 = (const float*)d_in[2];
    const float* b1 = (const float*)d_in[3];
    const float* W2 = (const float*)d_in[4];
    const float* b2 = (const float*)d_in[5];
    const float* Wf = (const float*)d_in[6];
    const float* bf = (const float*)d_in[7];
    float* out = (float*)d_out;

    int n = in_sizes[0] / IN_CH;   // 100000
    int E = in_sizes[1] / 2;       // 1600000

    int gblocks = (n + 63) / 64;
    gemm64_kernel<0><<<gblocks, 256>>>(nf, W1, b1, n);   // Y + zero H1/Z/deg

    long long work = (long long)E * 16;
    int sblocks = (int)((work + 255) / 256);
    scatter_kernel<0><<<sblocks, 256>>>(ei, E);
    scatter_kernel<1><<<sblocks, 256>>>(ei, E);

    gemm64_kernel<1><<<gblocks, 256>>>(nullptr, W2, b2, n);  // H2 -> g_Y4
    dense2b_kernel<<<(n + 255) / 256, 256>>>(Wf, bf, out, n);
}